// round 2
// baseline (speedup 1.0000x reference)
#include <cuda_runtime.h>

// PhonologicalLoopMemory:
//   out[b] = concat(recent[0..3], rehearsal), each segment FEATURE_DIM*WINDOW_LEN = 32768 f32.
//   recent[0] = features[b]            (buf was just overwritten at old_pos -> undecayed)
//   recent[j] = valid_j ? 0.9 * feature_buffer[b, (pos[b]-j) mod 64] : 0   (j=1..3)
//   rehearsal = features[b]
//   valid_j = buffer_filled[b] || (j <= pos[b])
//
// BATCH=64, BUFFER_LEN=64, SEG = 128*256 = 32768 floats = 8192 float4.
// buffer_filled arrives as int32 (bool upcast by harness) -- read as const int*.

#define SEG_F4   8192   // 32768 floats / 4
#define BUF_LEN  64
#define NSEG     5

__global__ __launch_bounds__(256) void phono_kernel(
    const float4* __restrict__ feat,          // [B, 8192]
    const float4* __restrict__ fbuf,          // [B, 64, 8192]
    const int*    __restrict__ cur_pos,       // [B]
    const int*    __restrict__ filled,        // [B] int32 (bool upcast)
    float4* __restrict__ out)                 // [B, 5, 8192]
{
    const int bj = blockIdx.y;        // b*5 + j
    const int b  = bj / NSEG;
    const int j  = bj - b * NSEG;
    const int i  = blockIdx.x * blockDim.x + threadIdx.x;  // 0..SEG_F4-1

    float4 v;
    if (j == 0 || j == 4) {
        v = feat[b * SEG_F4 + i];
    } else {
        const int p = cur_pos[b];
        const bool valid = (filled[b] != 0) || (j <= p);
        if (valid) {
            const int src = (p - j + BUF_LEN) & (BUF_LEN - 1);
            v = fbuf[(b * BUF_LEN + src) * SEG_F4 + i];
            v.x *= 0.9f; v.y *= 0.9f; v.z *= 0.9f; v.w *= 0.9f;
        } else {
            v = make_float4(0.f, 0.f, 0.f, 0.f);
        }
    }
    out[bj * SEG_F4 + i] = v;
}

extern "C" void kernel_launch(void* const* d_in, const int* in_sizes, int n_in,
                              void* d_out, int out_size)
{
    const float4* feat   = (const float4*)d_in[0];
    const float4* fbuf   = (const float4*)d_in[1];
    const int*    pos    = (const int*)d_in[2];
    const int*    filled = (const int*)d_in[3];
    float4*       out    = (float4*)d_out;

    const int batch = in_sizes[2];            // 64
    dim3 block(256);
    dim3 grid(SEG_F4 / 256, batch * NSEG);    // (32, 320)
    phono_kernel<<<grid, block>>>(feat, fbuf, pos, filled, out);
}